// round 2
// baseline (speedup 1.0000x reference)
#include <cuda_runtime.h>
#include <math.h>

#define RES      256
#define NTRI     1000
#define NBATCH   2
#define EPSF     1e-8f
#define PF       12              // A0 B0 C0 A1 B1 C1 A2 B2 C2 mn inv flag
#define TILE     16
#define NTILES   256             // (RES/TILE)^2

// scratch
__device__ float g_params[NBATCH * NTRI * PF];
__device__ int4  g_bbox[NBATCH * NTRI];                 // {x0, x1, y0, y1} inclusive; empty = {RES,-1,RES,-1}
__device__ int   g_tileCnt[NBATCH * NTILES];
__device__ int   g_tileList[NBATCH * NTILES * NTRI];

// ---------------------------------------------------------------------------
// Kernel 1: projection, edge coefficients, corner-rule interior flag, bbox.
// One thread per (b, t).  term_i(px,py) = A_i + B_i*px + C_i*py
// ---------------------------------------------------------------------------
__global__ void setup_kernel(const float* __restrict__ meshes,
                             const float* __restrict__ K,
                             const int*   __restrict__ model_idxs,
                             const float* __restrict__ poses)
{
    const int gid = blockIdx.x * blockDim.x + threadIdx.x;
    if (gid >= NBATCH * NTRI) return;
    const int b = gid / NTRI;
    const int t = gid - b * NTRI;

    // M = K @ cam  (3x4)
    float M[12];
    const float* cam = poses + b * 12;
    #pragma unroll
    for (int r = 0; r < 3; r++)
        #pragma unroll
        for (int c = 0; c < 4; c++) {
            float s = 0.0f;
            #pragma unroll
            for (int k = 0; k < 3; k++)
                s += K[r * 3 + k] * cam[k * 4 + c];
            M[r * 4 + c] = s;
        }

    const float* mesh = meshes + ((size_t)model_idxs[b] * NTRI + t) * 9;
    float vx[3], vy[3];
    #pragma unroll
    for (int j = 0; j < 3; j++) {
        float X = mesh[j * 3 + 0], Y = mesh[j * 3 + 1], Z = mesh[j * 3 + 2];
        float x = M[0] * X + M[1] * Y + M[2]  * Z + M[3];
        float y = M[4] * X + M[5] * Y + M[6]  * Z + M[7];
        float w = M[8] * X + M[9] * Y + M[10] * Z + M[11];
        float iw = 1.0f / (w + EPSF);
        vx[j] = x * iw;
        vy[j] = y * iw;
    }

    const float e0x = vx[1] - vx[0], e0y = vy[1] - vy[0];
    const float e1x = vx[2] - vx[1], e1y = vy[2] - vy[1];
    const float e2x = vx[0] - vx[2], e2y = vy[0] - vy[2];
    const float N = e0x * e2y - e0y * e2x + EPSF;

    const float A0 = N * (e0x * vy[0] - e0y * vx[0]), B0 =  N * e0y, C0 = -N * e0x;
    const float A1 = N * (e1x * vy[1] - e1y * vx[1]), B1 =  N * e1y, C1 = -N * e1x;
    const float A2 = N * (e2x * vy[2] - e2y * vx[2]), B2 =  N * e2y, C2 = -N * e2x;

    // corner rule: all three edge terms strictly positive at all 4 image corners
    // -> no clamping anywhere on the image rectangle -> grid min is interior-exact
    // (handled by full scan in max_kernel). Otherwise mn = 0 exactly.
    bool inter = true;
    #pragma unroll
    for (int c = 0; c < 4; c++) {
        float cx = (c & 1) ? (float)(RES - 1) : 0.0f;
        float cy = (c & 2) ? (float)(RES - 1) : 0.0f;
        inter = inter && (fmaf(C0, cy, fmaf(B0, cx, A0)) > 0.0f)
                      && (fmaf(C1, cy, fmaf(B1, cx, A1)) > 0.0f)
                      && (fmaf(C2, cy, fmaf(B2, cx, A2)) > 0.0f);
    }

    // conservative bbox of the score support (triangle of projected verts) +1px FP margin
    float fx0 = fminf(fminf(vx[0], vx[1]), vx[2]) - 1.0f;
    float fx1 = fmaxf(fmaxf(vx[0], vx[1]), vx[2]) + 1.0f;
    float fy0 = fminf(fminf(vy[0], vy[1]), vy[2]) - 1.0f;
    float fy1 = fmaxf(fmaxf(vy[0], vy[1]), vy[2]) + 1.0f;

    int4 bb;
    if (isfinite(fx0) && isfinite(fx1) && isfinite(fy0) && isfinite(fy1)) {
        int x0 = (fx0 < 0.0f) ? 0 : ((fx0 > (float)(RES - 1)) ? RES : (int)fx0);
        int x1 = (fx1 > (float)(RES - 1)) ? (RES - 1) : ((fx1 < 0.0f) ? -1 : (int)fx1);
        int y0 = (fy0 < 0.0f) ? 0 : ((fy0 > (float)(RES - 1)) ? RES : (int)fy0);
        int y1 = (fy1 > (float)(RES - 1)) ? (RES - 1) : ((fy1 < 0.0f) ? -1 : (int)fy1);
        if (x0 > x1 || y0 > y1) { x0 = RES; x1 = -1; y0 = RES; y1 = -1; }
        bb = make_int4(x0, x1, y0, y1);
    } else {
        bb = make_int4(0, RES - 1, 0, RES - 1);   // non-finite: be maximally conservative
    }

    float* P = g_params + (size_t)gid * PF;
    P[0] = A0; P[1] = B0; P[2]  = C0;
    P[3] = A1; P[4] = B1; P[5]  = C1;
    P[6] = A2; P[7] = B2; P[8]  = C2;
    P[9] = 0.0f; P[10] = 0.0f; P[11] = inter ? 1.0f : 0.0f;
    g_bbox[gid] = bb;
}

// ---------------------------------------------------------------------------
// Kernel 2: per-triangle max (and, in the rare interior case, min) of score
// over the bbox pixels. One block of 128 threads per (b, t).
// Evaluation order identical to raster_kernel.
// ---------------------------------------------------------------------------
__global__ void max_kernel()
{
    const int bt = blockIdx.x;
    float* P = g_params + (size_t)bt * PF;
    const int4 bb = g_bbox[bt];

    const float A0 = P[0], B0 = P[1], C0 = P[2];
    const float A1 = P[3], B1 = P[4], C1 = P[5];
    const float A2 = P[6], B2 = P[7], C2 = P[8];
    const float flag = P[11];

    const int w = bb.y - bb.x + 1;
    const int h = bb.w - bb.z + 1;
    const int n = (w > 0 && h > 0) ? w * h : 0;

    float mx = 0.0f;            // excluded pixels score exactly 0
    float mnl = INFINITY;
    for (int i = threadIdx.x; i < n; i += blockDim.x) {
        int px = bb.x + i / h;
        int py = bb.z + (i - (i / h) * h);
        float fx = (float)px, fy = (float)py;
        float t0 = fmaxf(fmaf(C0, fy, fmaf(B0, fx, A0)), 0.0f);
        float t1 = fmaxf(fmaf(C1, fy, fmaf(B1, fx, A1)), 0.0f);
        float t2 = fmaxf(fmaf(C2, fy, fmaf(B2, fx, A2)), 0.0f);
        float s = t0 * t1 * t2;
        mx  = fmaxf(mx, s);
        mnl = fminf(mnl, s);
    }

    #pragma unroll
    for (int o = 16; o > 0; o >>= 1) {
        mx  = fmaxf(mx,  __shfl_xor_sync(0xffffffffu, mx,  o));
        mnl = fminf(mnl, __shfl_xor_sync(0xffffffffu, mnl, o));
    }
    __shared__ float smx[4], smn[4];
    const int wid = threadIdx.x >> 5, lid = threadIdx.x & 31;
    if (lid == 0) { smx[wid] = mx; smn[wid] = mnl; }
    __syncthreads();
    if (threadIdx.x == 0) {
        float rmx = smx[0], rmn = smn[0];
        #pragma unroll
        for (int i = 1; i < 4; i++) {
            rmx = fmaxf(rmx, smx[i]);
            rmn = fminf(rmn, smn[i]);
        }
        // flag set => whole image strictly inside triangle => bbox == full image,
        // so rmn is the exact grid min. Otherwise grid min is exactly 0.
        float mn = (flag != 0.0f && n > 0) ? rmn : 0.0f;
        P[9]  = mn;
        P[10] = 1.0f / (rmx - mn + EPSF);
    }
}

// ---------------------------------------------------------------------------
// Kernel 3: deterministic, order-preserving tile binning.
// One warp per (b, tile); ballot-compaction keeps triangle order ascending.
// ---------------------------------------------------------------------------
__global__ void bin_kernel()
{
    const int gwid = (blockIdx.x * blockDim.x + threadIdx.x) >> 5;
    const int lane = threadIdx.x & 31;
    if (gwid >= NBATCH * NTILES) return;

    const int b    = gwid / NTILES;
    const int tile = gwid - b * NTILES;
    const int xlo = (tile >> 4) * TILE, xhi = xlo + TILE - 1;
    const int ylo = (tile & 15) * TILE, yhi = ylo + TILE - 1;

    int* list = g_tileList + (size_t)gwid * NTRI;
    const int4* bb = g_bbox + (size_t)b * NTRI;

    int cnt = 0;
    for (int base = 0; base < NTRI; base += 32) {
        const int t = base + lane;
        bool ok = false;
        if (t < NTRI) {
            int4 B = bb[t];
            ok = (B.x <= xhi) && (B.y >= xlo) && (B.z <= yhi) && (B.w >= ylo);
        }
        unsigned m = __ballot_sync(0xffffffffu, ok);
        if (ok) list[cnt + __popc(m & ((1u << lane) - 1u))] = t;
        cnt += __popc(m);
    }
    if (lane == 0) g_tileCnt[gwid] = cnt;
}

// ---------------------------------------------------------------------------
// Kernel 4: tile raster. Block = 256 threads = one 16x16 tile, one px each.
// Only triangles whose bbox touches the tile are evaluated; all skipped
// (tri, px) pairs contribute exactly tanh(0) = 0 in the reference.
// ---------------------------------------------------------------------------
__global__ void raster_kernel(float* __restrict__ out)
{
    const int b = blockIdx.y, tile = blockIdx.x;
    const int px = (tile >> 4) * TILE + (threadIdx.x >> 4);
    const int py = (tile & 15) * TILE + (threadIdx.x & 15);
    const float fx = (float)px, fy = (float)py;

    const int  cnt  = g_tileCnt[b * NTILES + tile];
    const int* list = g_tileList + (size_t)(b * NTILES + tile) * NTRI;
    const float4* __restrict__ q = (const float4*)(g_params + (size_t)b * NTRI * PF);

    float acc = 0.0f;
    for (int i = 0; i < cnt; i++) {
        const int t = list[i];
        float4 q0 = q[t * 3 + 0];   // A0 B0 C0 A1
        float4 q1 = q[t * 3 + 1];   // B1 C1 A2 B2
        float4 q2 = q[t * 3 + 2];   // C2 mn inv flag

        float t0 = fmaxf(fmaf(q0.z, fy, fmaf(q0.y, fx, q0.x)), 0.0f);
        float t1 = fmaxf(fmaf(q1.y, fy, fmaf(q1.x, fx, q0.w)), 0.0f);
        float t2 = fmaxf(fmaf(q2.x, fy, fmaf(q1.w, fx, q1.z)), 0.0f);
        float s  = t0 * t1 * t2;
        float d  = s - q2.y;
        if (d > 0.0f)
            acc += tanhf(d * q2.z);
    }

    out[(size_t)b * (RES * RES) + px * RES + py] = acc;
}

// ---------------------------------------------------------------------------
extern "C" void kernel_launch(void* const* d_in, const int* in_sizes, int n_in,
                              void* d_out, int out_size)
{
    const float* meshes = (const float*)d_in[0];
    const float* K      = (const float*)d_in[1];
    const int*   idxs   = (const int*)  d_in[2];
    const float* poses  = (const float*)d_in[3];
    float*       out    = (float*)d_out;

    setup_kernel<<<(NBATCH * NTRI + 255) / 256, 256>>>(meshes, K, idxs, poses);
    max_kernel<<<NBATCH * NTRI, 128>>>();
    bin_kernel<<<(NBATCH * NTILES * 32 + 255) / 256, 256>>>();

    dim3 g(NTILES, NBATCH);
    raster_kernel<<<g, 256>>>(out);
}

// round 3
// speedup vs baseline: 2.4239x; 2.4239x over previous
#include <cuda_runtime.h>
#include <math.h>

#define RES      256
#define NTRI     1000
#define NBATCH   2
#define EPSF     1e-8f
#define PF       12              // A0 B0 C0 A1 B1 C1 A2 B2 C2 mn inv pad
#define NPIX     (RES * RES)
#define SCALEF   16777216.0f     // 2^24 fixed-point scale
#define INVSCALE (1.0f / 16777216.0f)

// scratch
__device__ float              g_params[NBATCH * NTRI * PF];
__device__ int4               g_bbox[NBATCH * NTRI];      // {x0,x1,y0,y1} incl; empty: x0>x1
__device__ unsigned long long g_accum[NBATCH * NPIX];

// ---------------------------------------------------------------------------
// Kernel 1: zero the fixed-point accumulator (graph replays need this).
// ---------------------------------------------------------------------------
__global__ void zero_kernel()
{
    const int i = blockIdx.x * blockDim.x + threadIdx.x;
    if (i < NBATCH * NPIX) g_accum[i] = 0ull;
}

// ---------------------------------------------------------------------------
// Kernel 2: fused setup + bbox max/min scan. One block per (b,t), 64x2 thr.
//  thread 0: projection, edge coefficients term_i = A_i + B_i*px + C_i*py,
//            interior-corner flag, conservative bbox (+degeneracy guard).
//  all:      scan bbox pixels for max (and min, for the rare interior case).
// Pixels outside the bbox score exactly 0, so mx = bbox-max, mn = 0 unless
// the whole image is strictly inside the triangle (then bbox == full image
// and the scan min is the exact grid min).
// ---------------------------------------------------------------------------
__global__ void setupmax_kernel(const float* __restrict__ meshes,
                                const float* __restrict__ K,
                                const int*   __restrict__ model_idxs,
                                const float* __restrict__ poses)
{
    const int bt = blockIdx.x;
    const int b  = bt / NTRI;
    const int t  = bt - b * NTRI;
    const int tid = threadIdx.y * 64 + threadIdx.x;

    __shared__ float sP[9];
    __shared__ int4  sBB;
    __shared__ int   sFlag;

    if (tid == 0) {
        // M = K @ cam (3x4)
        float M[12];
        const float* cam = poses + b * 12;
        #pragma unroll
        for (int r = 0; r < 3; r++)
            #pragma unroll
            for (int c = 0; c < 4; c++) {
                float s = 0.0f;
                #pragma unroll
                for (int k = 0; k < 3; k++)
                    s += K[r * 3 + k] * cam[k * 4 + c];
                M[r * 4 + c] = s;
            }

        const float* mesh = meshes + ((size_t)model_idxs[b] * NTRI + t) * 9;
        float vx[3], vy[3];
        #pragma unroll
        for (int j = 0; j < 3; j++) {
            float X = mesh[j * 3 + 0], Y = mesh[j * 3 + 1], Z = mesh[j * 3 + 2];
            float x = M[0] * X + M[1] * Y + M[2]  * Z + M[3];
            float y = M[4] * X + M[5] * Y + M[6]  * Z + M[7];
            float w = M[8] * X + M[9] * Y + M[10] * Z + M[11];
            float iw = 1.0f / (w + EPSF);
            vx[j] = x * iw;
            vy[j] = y * iw;
        }

        const float e0x = vx[1] - vx[0], e0y = vy[1] - vy[0];
        const float e1x = vx[2] - vx[1], e1y = vy[2] - vy[1];
        const float e2x = vx[0] - vx[2], e2y = vy[0] - vy[2];
        const float N = e0x * e2y - e0y * e2x + EPSF;

        const float A0 = N * (e0x * vy[0] - e0y * vx[0]), B0 =  N * e0y, C0 = -N * e0x;
        const float A1 = N * (e1x * vy[1] - e1y * vx[1]), B1 =  N * e1y, C1 = -N * e1x;
        const float A2 = N * (e2x * vy[2] - e2y * vx[2]), B2 =  N * e2y, C2 = -N * e2x;

        // corner rule: all terms strictly positive at all 4 image corners
        bool inter = true;
        #pragma unroll
        for (int c = 0; c < 4; c++) {
            float cx = (c & 1) ? (float)(RES - 1) : 0.0f;
            float cy = (c & 2) ? (float)(RES - 1) : 0.0f;
            inter = inter && (fmaf(C0, cy, fmaf(B0, cx, A0)) > 0.0f)
                          && (fmaf(C1, cy, fmaf(B1, cx, A1)) > 0.0f)
                          && (fmaf(C2, cy, fmaf(B2, cx, A2)) > 0.0f);
        }

        // conservative bbox (+1px margin), clipped to image
        float fx0 = fminf(fminf(vx[0], vx[1]), vx[2]) - 1.0f;
        float fx1 = fmaxf(fmaxf(vx[0], vx[1]), vx[2]) + 1.0f;
        float fy0 = fminf(fminf(vy[0], vy[1]), vy[2]) - 1.0f;
        float fy1 = fmaxf(fmaxf(vy[0], vy[1]), vy[2]) + 1.0f;

        bool safe = isfinite(fx0) && isfinite(fx1) && isfinite(fy0) && isfinite(fy1)
                    && fabsf(N) > 1e-6f;   // near-degenerate: support may escape bbox

        int4 bb;
        if (safe) {
            int x0 = (fx0 < 0.0f) ? 0 : ((fx0 > (float)(RES - 1)) ? RES : (int)fx0);
            int x1 = (fx1 > (float)(RES - 1)) ? (RES - 1) : ((fx1 < 0.0f) ? -1 : (int)fx1);
            int y0 = (fy0 < 0.0f) ? 0 : ((fy0 > (float)(RES - 1)) ? RES : (int)fy0);
            int y1 = (fy1 > (float)(RES - 1)) ? (RES - 1) : ((fy1 < 0.0f) ? -1 : (int)fy1);
            if (x0 > x1 || y0 > y1) { x0 = RES; x1 = -1; y0 = RES; y1 = -1; }
            bb = make_int4(x0, x1, y0, y1);
        } else {
            bb = make_int4(0, RES - 1, 0, RES - 1);
        }

        sP[0] = A0; sP[1] = B0; sP[2] = C0;
        sP[3] = A1; sP[4] = B1; sP[5] = C1;
        sP[6] = A2; sP[7] = B2; sP[8] = C2;
        sBB   = bb;
        sFlag = inter ? 1 : 0;

        float* P = g_params + (size_t)bt * PF;
        #pragma unroll
        for (int i = 0; i < 9; i++) P[i] = sP[i];
        P[11] = 0.0f;
        g_bbox[bt] = bb;
    }
    __syncthreads();

    const int4 bb = sBB;
    const float A0 = sP[0], B0 = sP[1], C0 = sP[2];
    const float A1 = sP[3], B1 = sP[4], C1 = sP[5];
    const float A2 = sP[6], B2 = sP[7], C2 = sP[8];

    float mx  = 0.0f;          // excluded pixels score exactly 0
    float mnl = INFINITY;
    bool any = false;
    for (int yy = bb.z + threadIdx.y; yy <= bb.w; yy += 2) {
        const float fy = (float)yy;
        const float r0 = fmaf(C0, fy, A0);
        const float r1 = fmaf(C1, fy, A1);
        const float r2 = fmaf(C2, fy, A2);
        for (int xx = bb.x + threadIdx.x; xx <= bb.y; xx += 64) {
            const float fx = (float)xx;
            float t0 = fmaxf(fmaf(C0, fy, fmaf(B0, fx, A0)), 0.0f);
            float t1 = fmaxf(fmaf(C1, fy, fmaf(B1, fx, A1)), 0.0f);
            float t2 = fmaxf(fmaf(C2, fy, fmaf(B2, fx, A2)), 0.0f);
            float s = t0 * t1 * t2;
            mx  = fmaxf(mx, s);
            mnl = fminf(mnl, s);
            any = true;
        }
        (void)r0; (void)r1; (void)r2;
    }

    #pragma unroll
    for (int o = 16; o > 0; o >>= 1) {
        mx  = fmaxf(mx,  __shfl_xor_sync(0xffffffffu, mx,  o));
        mnl = fminf(mnl, __shfl_xor_sync(0xffffffffu, mnl, o));
    }
    __shared__ float smx[4], smn[4];
    const int wid = tid >> 5, lid = tid & 31;
    if (lid == 0) { smx[wid] = mx; smn[wid] = mnl; }
    __syncthreads();
    if (tid == 0) {
        float rmx = smx[0], rmn = smn[0];
        #pragma unroll
        for (int i = 1; i < 4; i++) {
            rmx = fmaxf(rmx, smx[i]);
            rmn = fminf(rmn, smn[i]);
        }
        const bool fullimg = (sBB.x == 0) && (sBB.y == RES - 1) &&
                             (sBB.z == 0) && (sBB.w == RES - 1);
        float mn = (sFlag && fullimg) ? rmn : 0.0f;
        float* P = g_params + (size_t)bt * PF;
        P[9]  = mn;
        P[10] = 1.0f / (rmx - mn + EPSF);
    }
    (void)any;
}

// ---------------------------------------------------------------------------
// Kernel 3: per-triangle scatter over its bbox. One block per (b,t), 64x4 thr.
// Fixed-point u64 atomics => bitwise-deterministic accumulation.
// Evaluation order identical to the max scan, so s >= mn holds exactly and
// the d>0 skip equals tanh(0)=0 contributions in the reference.
// ---------------------------------------------------------------------------
__global__ void scatter_kernel()
{
    const int bt = blockIdx.x;
    const int b  = bt / NTRI;

    const float4* __restrict__ q = (const float4*)(g_params + (size_t)bt * PF);
    const float4 q0 = q[0];   // A0 B0 C0 A1
    const float4 q1 = q[1];   // B1 C1 A2 B2
    const float4 q2 = q[2];   // C2 mn inv pad
    const int4   bb = g_bbox[bt];

    unsigned long long* __restrict__ acc = g_accum + (size_t)b * NPIX;

    for (int yy = bb.z + threadIdx.y; yy <= bb.w; yy += 4) {
        const float fy = (float)yy;
        for (int xx = bb.x + threadIdx.x; xx <= bb.y; xx += 64) {
            const float fx = (float)xx;
            float t0 = fmaxf(fmaf(q0.z, fy, fmaf(q0.y, fx, q0.x)), 0.0f);
            float t1 = fmaxf(fmaf(q1.y, fy, fmaf(q1.x, fx, q0.w)), 0.0f);
            float t2 = fmaxf(fmaf(q2.x, fy, fmaf(q1.w, fx, q1.z)), 0.0f);
            float s  = t0 * t1 * t2;
            float d  = s - q2.y;
            if (d > 0.0f) {
                float v = tanhf(d * q2.z);
                unsigned long long fp = __float2ull_rn(v * SCALEF);
                atomicAdd(acc + xx * RES + yy, fp);
            }
        }
    }
}

// ---------------------------------------------------------------------------
// Kernel 4: fixed point -> float output.
// ---------------------------------------------------------------------------
__global__ void finalize_kernel(float* __restrict__ out)
{
    const int i = blockIdx.x * blockDim.x + threadIdx.x;
    if (i < NBATCH * NPIX)
        out[i] = (float)g_accum[i] * INVSCALE;
}

// ---------------------------------------------------------------------------
extern "C" void kernel_launch(void* const* d_in, const int* in_sizes, int n_in,
                              void* d_out, int out_size)
{
    const float* meshes = (const float*)d_in[0];
    const float* K      = (const float*)d_in[1];
    const int*   idxs   = (const int*)  d_in[2];
    const float* poses  = (const float*)d_in[3];
    float*       out    = (float*)d_out;

    zero_kernel<<<(NBATCH * NPIX + 255) / 256, 256>>>();

    dim3 t1(64, 2);
    setupmax_kernel<<<NBATCH * NTRI, t1>>>(meshes, K, idxs, poses);

    dim3 t2(64, 4);
    scatter_kernel<<<NBATCH * NTRI, t2>>>();

    finalize_kernel<<<(NBATCH * NPIX + 255) / 256, 256>>>(out);
}

// round 4
// speedup vs baseline: 5.0198x; 2.0710x over previous
#include <cuda_runtime.h>
#include <math.h>

#define RES      256
#define NTRI     1000
#define NBATCH   2
#define EPSF     1e-8f
#define NPIX     (RES * RES)
#define NPAIR    (NPIX / 2)          // y-pairs packed in u64
#define SCALEF   2097152.0f          // 2^21
#define INVSCALE (1.0f / 2097152.0f)

// u64 accumulator: low 32 = y even, high 32 = y odd. addr = b*NPAIR + x*128 + (y>>1)
__device__ unsigned long long g_accum[NBATCH * NPAIR];

struct Coef { float A0,B0,C0, A1,B1,C1, A2,B2,C2; };

// exact score evaluation — must be the SAME formula everywhere
__device__ __forceinline__ float eval_s(const Coef& c, float fx, float fy)
{
    float t0 = fmaxf(fmaf(c.C0, fy, fmaf(c.B0, fx, c.A0)), 0.0f);
    float t1 = fmaxf(fmaf(c.C1, fy, fmaf(c.B1, fx, c.A1)), 0.0f);
    float t2 = fmaxf(fmaf(c.C2, fy, fmaf(c.B2, fx, c.A2)), 0.0f);
    return t0 * t1 * t2;
}

// Pade/continued-fraction tanh, ~1e-7 accurate on [0, ~1.1]; branch-free
__device__ __forceinline__ float tanh_pade(float x)
{
    float t   = x * x;
    float num = fmaf(t, fmaf(t, 21.0f, 1260.0f), 10395.0f);
    float den = fmaf(t, fmaf(t, fmaf(t, 1.0f, 210.0f), 4725.0f), 10395.0f);
    return x * __fdividef(num, den);
}

// positive-interval [lo,hi] of row fy (normalized coeffs); empty -> lo > hi
__device__ __forceinline__ void row_iv(const Coef& n, float fy, float& lo, float& hi)
{
    float a0 = fmaf(n.C0, fy, n.A0);
    float a1 = fmaf(n.C1, fy, n.A1);
    float a2 = fmaf(n.C2, fy, n.A2);
    lo = -1e30f; hi = 1e30f;
    if (n.B0 >  1e-25f)      lo = fmaxf(lo, -__fdividef(a0, n.B0));
    else if (n.B0 < -1e-25f) hi = fminf(hi, -__fdividef(a0, n.B0));
    else if (a0 <= 0.0f)   { lo = 1e30f; hi = -1e30f; return; }
    if (n.B1 >  1e-25f)      lo = fmaxf(lo, -__fdividef(a1, n.B1));
    else if (n.B1 < -1e-25f) hi = fminf(hi, -__fdividef(a1, n.B1));
    else if (a1 <= 0.0f)   { lo = 1e30f; hi = -1e30f; return; }
    if (n.B2 >  1e-25f)      lo = fmaxf(lo, -__fdividef(a2, n.B2));
    else if (n.B2 < -1e-25f) hi = fminf(hi, -__fdividef(a2, n.B2));
    else if (a2 <= 0.0f)   { lo = 1e30f; hi = -1e30f; return; }
}

// exact grid max of the clamped product over row y within [bb.x, bb.y]:
// log-concave on the positive interval -> unimodal -> grid argmax is at
// floor/ceil of a critical point (roots of quadratic f') or interval ends.
__device__ float row_max(const Coef& c, const Coef& n, const int4 bb, int y)
{
    const float fy = (float)y;
    float a0 = fmaf(n.C0, fy, n.A0);
    float a1 = fmaf(n.C1, fy, n.A1);
    float a2 = fmaf(n.C2, fy, n.A2);

    float lo = (float)bb.x, hi = (float)bb.y;
    bool ok = true;
    if (n.B0 >  1e-25f)      lo = fmaxf(lo, -__fdividef(a0, n.B0));
    else if (n.B0 < -1e-25f) hi = fminf(hi, -__fdividef(a0, n.B0));
    else                     ok = ok && (a0 > 0.0f);
    if (n.B1 >  1e-25f)      lo = fmaxf(lo, -__fdividef(a1, n.B1));
    else if (n.B1 < -1e-25f) hi = fminf(hi, -__fdividef(a1, n.B1));
    else                     ok = ok && (a1 > 0.0f);
    if (n.B2 >  1e-25f)      lo = fmaxf(lo, -__fdividef(a2, n.B2));
    else if (n.B2 < -1e-25f) hi = fminf(hi, -__fdividef(a2, n.B2));
    else                     ok = ok && (a2 > 0.0f);

    float clo = ceilf(lo), chi = floorf(hi);
    if (!ok || clo > chi) return 0.0f;

    // f'(x) = 0 : quadratic in x (normalized coeffs keep fp32 in range)
    float q2 = 3.0f * n.B0 * n.B1 * n.B2;
    float q1 = 2.0f * (n.B0*n.B1*a2 + n.B0*n.B2*a1 + n.B1*n.B2*a0);
    float q0 = n.B0*a1*a2 + n.B1*a0*a2 + n.B2*a0*a1;

    float xc1 = 0.5f * (clo + chi), xc2 = xc1;
    if (fabsf(q2) > 1e-30f) {
        float disc = fmaf(q1, q1, -4.0f * q2 * q0);
        float sq   = sqrtf(fmaxf(disc, 0.0f));
        float i2   = __fdividef(0.5f, q2);
        xc1 = (-q1 + sq) * i2;
        xc2 = (-q1 - sq) * i2;
    } else if (fabsf(q1) > 1e-30f) {
        xc1 = xc2 = -__fdividef(q0, q1);
    }

    float f1 = floorf(xc1), f2 = floorf(xc2);
    float cand[6] = { clo, chi, f1, f1 + 1.0f, f2, f2 + 1.0f };
    float m = 0.0f;
    #pragma unroll
    for (int i = 0; i < 6; i++) {
        float x = fminf(fmaxf(cand[i], clo), chi);   // NaN-safe: falls back to clo/chi
        m = fmaxf(m, eval_s(c, x, fy));
    }
    return m;
}

// ---------------------------------------------------------------------------
__global__ void zero_kernel()
{
    const int i = blockIdx.x * blockDim.x + threadIdx.x;
    if (i < NBATCH * NPAIR) g_accum[i] = 0ull;
}

// ---------------------------------------------------------------------------
// One block per (b, t): setup -> analytic max/min -> interval scatter.
// ---------------------------------------------------------------------------
__global__ void __launch_bounds__(256) fused_kernel(const float* __restrict__ meshes,
                                                    const float* __restrict__ K,
                                                    const int*   __restrict__ model_idxs,
                                                    const float* __restrict__ poses)
{
    const int bt  = blockIdx.x;
    const int b   = bt / NTRI;
    const int t   = bt - b * NTRI;
    const int tid = threadIdx.x;

    __shared__ Coef  sC, sN;
    __shared__ int4  sBB;
    __shared__ int   sFlag;
    __shared__ float sMn, sInv;
    __shared__ float swmax[8];

    // ---------------- thread 0: projection + coefficients + bbox ----------
    if (tid == 0) {
        float M[12];
        const float* cam = poses + b * 12;
        #pragma unroll
        for (int r = 0; r < 3; r++)
            #pragma unroll
            for (int cc = 0; cc < 4; cc++) {
                float s = 0.0f;
                #pragma unroll
                for (int k = 0; k < 3; k++)
                    s += K[r * 3 + k] * cam[k * 4 + cc];
                M[r * 4 + cc] = s;
            }

        const float* mesh = meshes + ((size_t)model_idxs[b] * NTRI + t) * 9;
        float vx[3], vy[3];
        #pragma unroll
        for (int j = 0; j < 3; j++) {
            float X = mesh[j*3+0], Y = mesh[j*3+1], Z = mesh[j*3+2];
            float x = M[0]*X + M[1]*Y + M[2] *Z + M[3];
            float y = M[4]*X + M[5]*Y + M[6] *Z + M[7];
            float w = M[8]*X + M[9]*Y + M[10]*Z + M[11];
            float iw = 1.0f / (w + EPSF);
            vx[j] = x * iw;  vy[j] = y * iw;
        }

        const float e0x = vx[1]-vx[0], e0y = vy[1]-vy[0];
        const float e1x = vx[2]-vx[1], e1y = vy[2]-vy[1];
        const float e2x = vx[0]-vx[2], e2y = vy[0]-vy[2];
        const float N = e0x * e2y - e0y * e2x + EPSF;

        Coef c;
        c.A0 = N*(e0x*vy[0]-e0y*vx[0]); c.B0 =  N*e0y; c.C0 = -N*e0x;
        c.A1 = N*(e1x*vy[1]-e1y*vx[1]); c.B1 =  N*e1y; c.C1 = -N*e1x;
        c.A2 = N*(e2x*vy[2]-e2y*vx[2]); c.B2 =  N*e2y; c.C2 = -N*e2x;

        // interior flag: all terms strictly positive at all 4 image corners
        bool inter = true;
        #pragma unroll
        for (int k = 0; k < 4; k++) {
            float cx = (k & 1) ? (float)(RES-1) : 0.0f;
            float cy = (k & 2) ? (float)(RES-1) : 0.0f;
            inter = inter && (fmaf(c.C0, cy, fmaf(c.B0, cx, c.A0)) > 0.0f)
                          && (fmaf(c.C1, cy, fmaf(c.B1, cx, c.A1)) > 0.0f)
                          && (fmaf(c.C2, cy, fmaf(c.B2, cx, c.A2)) > 0.0f);
        }

        // conservative bbox (+1px), clipped; degenerate -> full image
        float fx0 = fminf(fminf(vx[0],vx[1]),vx[2]) - 1.0f;
        float fx1 = fmaxf(fmaxf(vx[0],vx[1]),vx[2]) + 1.0f;
        float fy0 = fminf(fminf(vy[0],vy[1]),vy[2]) - 1.0f;
        float fy1 = fmaxf(fmaxf(vy[0],vy[1]),vy[2]) + 1.0f;
        bool safe = isfinite(fx0) && isfinite(fx1) && isfinite(fy0) && isfinite(fy1)
                    && fabsf(N) > 1e-6f;
        int4 bb;
        if (safe) {
            int x0 = (fx0 < 0.0f) ? 0 : ((fx0 > (float)(RES-1)) ? RES : (int)fx0);
            int x1 = (fx1 > (float)(RES-1)) ? (RES-1) : ((fx1 < 0.0f) ? -1 : (int)fx1);
            int y0 = (fy0 < 0.0f) ? 0 : ((fy0 > (float)(RES-1)) ? RES : (int)fy0);
            int y1 = (fy1 > (float)(RES-1)) ? (RES-1) : ((fy1 < 0.0f) ? -1 : (int)fy1);
            if (x0 > x1 || y0 > y1) { x0 = RES; x1 = -1; y0 = RES; y1 = -1; }
            bb = make_int4(x0, x1, y0, y1);
        } else {
            bb = make_int4(0, RES-1, 0, RES-1);
        }

        // per-triangle normalization for the analytic root math (scale-invariant)
        float kap = 0.0f;
        kap = fmaxf(kap, fabsf(c.A0)); kap = fmaxf(kap, 256.0f*fabsf(c.B0)); kap = fmaxf(kap, 256.0f*fabsf(c.C0));
        kap = fmaxf(kap, fabsf(c.A1)); kap = fmaxf(kap, 256.0f*fabsf(c.B1)); kap = fmaxf(kap, 256.0f*fabsf(c.C1));
        kap = fmaxf(kap, fabsf(c.A2)); kap = fmaxf(kap, 256.0f*fabsf(c.B2)); kap = fmaxf(kap, 256.0f*fabsf(c.C2));
        float rk = (kap > 1e-30f) ? (1.0f / kap) : 0.0f;
        Coef nn;
        nn.A0 = c.A0*rk; nn.B0 = c.B0*rk; nn.C0 = c.C0*rk;
        nn.A1 = c.A1*rk; nn.B1 = c.B1*rk; nn.C1 = c.C1*rk;
        nn.A2 = c.A2*rk; nn.B2 = c.B2*rk; nn.C2 = c.C2*rk;

        sC = c; sN = nn; sBB = bb; sFlag = inter ? 1 : 0;
    }
    __syncthreads();

    const Coef c  = sC;
    const Coef n  = sN;
    const int4 bb = sBB;

    // ---------------- phase 1: analytic per-row max --------------------------
    float mx = 0.0f;
    for (int y = bb.z + tid; y <= bb.w; y += 256)
        mx = fmaxf(mx, row_max(c, n, bb, y));

    #pragma unroll
    for (int o = 16; o > 0; o >>= 1)
        mx = fmaxf(mx, __shfl_xor_sync(0xffffffffu, mx, o));
    if ((tid & 31) == 0) swmax[tid >> 5] = mx;
    __syncthreads();
    if (tid == 0) {
        float rmx = swmax[0];
        #pragma unroll
        for (int i = 1; i < 8; i++) rmx = fmaxf(rmx, swmax[i]);
        // interior case: log-concave => quasi-concave => grid min at an image corner
        float mn = 0.0f;
        if (sFlag) {
            const float e = (float)(RES - 1);
            mn = eval_s(c, 0.0f, 0.0f);
            mn = fminf(mn, eval_s(c, e, 0.0f));
            mn = fminf(mn, eval_s(c, 0.0f, e));
            mn = fminf(mn, eval_s(c, e, e));
        }
        sMn  = mn;
        sInv = 1.0f / (rmx - mn + EPSF);
    }
    __syncthreads();

    const float mn  = sMn;
    const float inv = sInv;

    // ---------------- phase 2: interval scatter, y-paired u64 atomics --------
    const int wid  = tid >> 5;
    const int lane = tid & 31;
    const int k0 = bb.z >> 1;
    const int k1 = bb.w >> 1;
    unsigned long long* __restrict__ acc = g_accum + (size_t)b * NPAIR;

    for (int k = k0 + wid; k <= k1; k += 8) {
        const int   y0 = 2 * k, y1 = 2 * k + 1;
        const float fy0 = (float)y0, fy1 = (float)y1;

        float lo0, hi0, lo1, hi1;
        row_iv(n, fy0, lo0, hi0);
        row_iv(n, fy1, lo1, hi1);
        if (y0 < bb.z) { lo0 = 1e30f; hi0 = -1e30f; }   // rows outside bbox: s == 0 exactly
        if (y1 > bb.w) { lo1 = 1e30f; hi1 = -1e30f; }

        float xsf = fmaxf((float)bb.x, ceilf(fminf(lo0, lo1)) - 1.0f);
        float xef = fminf((float)bb.y, floorf(fmaxf(hi0, hi1)) + 1.0f);
        const int xs = (int)xsf;
        const int xe = (int)xef;

        for (int x = xs + lane; x <= xe; x += 32) {
            const float fx = (float)x;
            unsigned int v0 = 0u, v1 = 0u;
            float d0 = eval_s(c, fx, fy0) - mn;
            if (d0 > 0.0f) v0 = __float2uint_rn(tanh_pade(d0 * inv) * SCALEF);
            float d1 = eval_s(c, fx, fy1) - mn;
            if (d1 > 0.0f) v1 = __float2uint_rn(tanh_pade(d1 * inv) * SCALEF);
            unsigned long long p = (unsigned long long)v0
                                 | ((unsigned long long)v1 << 32);
            if (p) atomicAdd(acc + x * (RES / 2) + k, p);
        }
    }
}

// ---------------------------------------------------------------------------
__global__ void finalize_kernel(float* __restrict__ out)
{
    const int i = blockIdx.x * blockDim.x + threadIdx.x;
    if (i >= NBATCH * NPAIR) return;
    const unsigned long long p = g_accum[i];
    const int b = i / NPAIR;
    const int r = i - b * NPAIR;          // r = x*128 + k
    const int x = r >> 7;
    const int k = r & 127;
    float* o = out + (size_t)b * NPIX + x * RES + 2 * k;
    o[0] = (float)(unsigned int)(p)         * INVSCALE;
    o[1] = (float)(unsigned int)(p >> 32)   * INVSCALE;
}

// ---------------------------------------------------------------------------
extern "C" void kernel_launch(void* const* d_in, const int* in_sizes, int n_in,
                              void* d_out, int out_size)
{
    const float* meshes = (const float*)d_in[0];
    const float* K      = (const float*)d_in[1];
    const int*   idxs   = (const int*)  d_in[2];
    const float* poses  = (const float*)d_in[3];
    float*       out    = (float*)d_out;

    zero_kernel<<<(NBATCH * NPAIR + 255) / 256, 256>>>();
    fused_kernel<<<NBATCH * NTRI, 256>>>(meshes, K, idxs, poses);
    finalize_kernel<<<(NBATCH * NPAIR + 255) / 256, 256>>>(out);
}

// round 5
// speedup vs baseline: 5.2948x; 1.0548x over previous
#include <cuda_runtime.h>
#include <math.h>

#define RES      256
#define NTRI     1000
#define NBATCH   2
#define EPSF     1e-8f
#define NPIX     (RES * RES)
#define NPAIR    (NPIX / 2)          // y-pairs packed in u64
#define SCALEF   2097152.0f          // 2^21
#define INVSCALE (1.0f / 2097152.0f)
#define YSPLIT   2                   // scatter blocks per triangle

// u64 accumulator: low 32 = y even, high 32 = y odd. addr = b*NPAIR + x*128 + (y>>1)
// Zero-initialized at module load; finalize_kernel re-zeros it every launch.
__device__ unsigned long long g_accum[NBATCH * NPAIR];

struct Coef { float A0,B0,C0, A1,B1,C1, A2,B2,C2; };

// exact score evaluation — the SAME formula everywhere
__device__ __forceinline__ float eval_s(const Coef& c, float fx, float fy)
{
    float t0 = fmaxf(fmaf(c.C0, fy, fmaf(c.B0, fx, c.A0)), 0.0f);
    float t1 = fmaxf(fmaf(c.C1, fy, fmaf(c.B1, fx, c.A1)), 0.0f);
    float t2 = fmaxf(fmaf(c.C2, fy, fmaf(c.B2, fx, c.A2)), 0.0f);
    return t0 * t1 * t2;
}

// (5,4) continued-fraction Pade tanh, err <= ~2.4e-5 on [0, 1.05]; branch-free
__device__ __forceinline__ float tanh_pade(float x)
{
    float t   = x * x;
    float num = fmaf(t, fmaf(t, 1.0f, 105.0f), 945.0f);
    float den = fmaf(t, fmaf(t, 15.0f, 420.0f), 945.0f);
    return x * __fdividef(num, den);
}

// positive-interval [lo,hi] of row fy (normalized coeffs); empty -> lo > hi
__device__ __forceinline__ void row_iv(const Coef& n, float fy, float& lo, float& hi)
{
    float a0 = fmaf(n.C0, fy, n.A0);
    float a1 = fmaf(n.C1, fy, n.A1);
    float a2 = fmaf(n.C2, fy, n.A2);
    lo = -1e30f; hi = 1e30f;
    if (n.B0 >  1e-25f)      lo = fmaxf(lo, -__fdividef(a0, n.B0));
    else if (n.B0 < -1e-25f) hi = fminf(hi, -__fdividef(a0, n.B0));
    else if (a0 <= 0.0f)   { lo = 1e30f; hi = -1e30f; return; }
    if (n.B1 >  1e-25f)      lo = fmaxf(lo, -__fdividef(a1, n.B1));
    else if (n.B1 < -1e-25f) hi = fminf(hi, -__fdividef(a1, n.B1));
    else if (a1 <= 0.0f)   { lo = 1e30f; hi = -1e30f; return; }
    if (n.B2 >  1e-25f)      lo = fmaxf(lo, -__fdividef(a2, n.B2));
    else if (n.B2 < -1e-25f) hi = fminf(hi, -__fdividef(a2, n.B2));
    else if (a2 <= 0.0f)   { lo = 1e30f; hi = -1e30f; return; }
}

// exact grid max of the clamped product over row y within [bb.x, bb.y]
__device__ float row_max(const Coef& c, const Coef& n, const int4 bb, int y)
{
    const float fy = (float)y;
    float a0 = fmaf(n.C0, fy, n.A0);
    float a1 = fmaf(n.C1, fy, n.A1);
    float a2 = fmaf(n.C2, fy, n.A2);

    float lo = (float)bb.x, hi = (float)bb.y;
    bool ok = true;
    if (n.B0 >  1e-25f)      lo = fmaxf(lo, -__fdividef(a0, n.B0));
    else if (n.B0 < -1e-25f) hi = fminf(hi, -__fdividef(a0, n.B0));
    else                     ok = ok && (a0 > 0.0f);
    if (n.B1 >  1e-25f)      lo = fmaxf(lo, -__fdividef(a1, n.B1));
    else if (n.B1 < -1e-25f) hi = fminf(hi, -__fdividef(a1, n.B1));
    else                     ok = ok && (a1 > 0.0f);
    if (n.B2 >  1e-25f)      lo = fmaxf(lo, -__fdividef(a2, n.B2));
    else if (n.B2 < -1e-25f) hi = fminf(hi, -__fdividef(a2, n.B2));
    else                     ok = ok && (a2 > 0.0f);

    float clo = ceilf(lo), chi = floorf(hi);
    if (!ok || clo > chi) return 0.0f;

    // f'(x) = 0 : quadratic (normalized coeffs keep fp32 in range)
    float q2 = 3.0f * n.B0 * n.B1 * n.B2;
    float q1 = 2.0f * (n.B0*n.B1*a2 + n.B0*n.B2*a1 + n.B1*n.B2*a0);
    float q0 = n.B0*a1*a2 + n.B1*a0*a2 + n.B2*a0*a1;

    float xc1 = 0.5f * (clo + chi), xc2 = xc1;
    if (fabsf(q2) > 1e-30f) {
        float disc = fmaf(q1, q1, -4.0f * q2 * q0);
        float sq   = sqrtf(fmaxf(disc, 0.0f));
        float i2   = __fdividef(0.5f, q2);
        xc1 = (-q1 + sq) * i2;
        xc2 = (-q1 - sq) * i2;
    } else if (fabsf(q1) > 1e-30f) {
        xc1 = xc2 = -__fdividef(q0, q1);
    }

    float f1 = floorf(xc1), f2 = floorf(xc2);
    float cand[6] = { clo, chi, f1, f1 + 1.0f, f2, f2 + 1.0f };
    float m = 0.0f;
    #pragma unroll
    for (int i = 0; i < 6; i++) {
        float x = fminf(fmaxf(cand[i], clo), chi);   // NaN-safe
        m = fmaxf(m, eval_s(c, x, fy));
    }
    return m;
}

// ---------------------------------------------------------------------------
// grid = (NBATCH*NTRI, YSPLIT). Each block: setup + analytic max (duplicated
// across the YSPLIT siblings), then scatters its share of row-pairs.
// ---------------------------------------------------------------------------
__global__ void __launch_bounds__(256) fused_kernel(const float* __restrict__ meshes,
                                                    const float* __restrict__ K,
                                                    const int*   __restrict__ model_idxs,
                                                    const float* __restrict__ poses)
{
    const int bt  = blockIdx.x;
    const int b   = bt / NTRI;
    const int t   = bt - b * NTRI;
    const int tid = threadIdx.x;

    __shared__ Coef  sC, sN;
    __shared__ int4  sBB;
    __shared__ int   sFlag;
    __shared__ float sMn, sInv;
    __shared__ float swmax[8];

    if (tid == 0) {
        float M[12];
        const float* cam = poses + b * 12;
        #pragma unroll
        for (int r = 0; r < 3; r++)
            #pragma unroll
            for (int cc = 0; cc < 4; cc++) {
                float s = 0.0f;
                #pragma unroll
                for (int k = 0; k < 3; k++)
                    s += K[r * 3 + k] * cam[k * 4 + cc];
                M[r * 4 + cc] = s;
            }

        const float* mesh = meshes + ((size_t)model_idxs[b] * NTRI + t) * 9;
        float vx[3], vy[3];
        #pragma unroll
        for (int j = 0; j < 3; j++) {
            float X = mesh[j*3+0], Y = mesh[j*3+1], Z = mesh[j*3+2];
            float x = M[0]*X + M[1]*Y + M[2] *Z + M[3];
            float y = M[4]*X + M[5]*Y + M[6] *Z + M[7];
            float w = M[8]*X + M[9]*Y + M[10]*Z + M[11];
            float iw = 1.0f / (w + EPSF);
            vx[j] = x * iw;  vy[j] = y * iw;
        }

        const float e0x = vx[1]-vx[0], e0y = vy[1]-vy[0];
        const float e1x = vx[2]-vx[1], e1y = vy[2]-vy[1];
        const float e2x = vx[0]-vx[2], e2y = vy[0]-vy[2];
        const float N = e0x * e2y - e0y * e2x + EPSF;

        Coef c;
        c.A0 = N*(e0x*vy[0]-e0y*vx[0]); c.B0 =  N*e0y; c.C0 = -N*e0x;
        c.A1 = N*(e1x*vy[1]-e1y*vx[1]); c.B1 =  N*e1y; c.C1 = -N*e1x;
        c.A2 = N*(e2x*vy[2]-e2y*vx[2]); c.B2 =  N*e2y; c.C2 = -N*e2x;

        bool inter = true;
        #pragma unroll
        for (int k = 0; k < 4; k++) {
            float cx = (k & 1) ? (float)(RES-1) : 0.0f;
            float cy = (k & 2) ? (float)(RES-1) : 0.0f;
            inter = inter && (fmaf(c.C0, cy, fmaf(c.B0, cx, c.A0)) > 0.0f)
                          && (fmaf(c.C1, cy, fmaf(c.B1, cx, c.A1)) > 0.0f)
                          && (fmaf(c.C2, cy, fmaf(c.B2, cx, c.A2)) > 0.0f);
        }

        float fx0 = fminf(fminf(vx[0],vx[1]),vx[2]) - 1.0f;
        float fx1 = fmaxf(fmaxf(vx[0],vx[1]),vx[2]) + 1.0f;
        float fy0 = fminf(fminf(vy[0],vy[1]),vy[2]) - 1.0f;
        float fy1 = fmaxf(fmaxf(vy[0],vy[1]),vy[2]) + 1.0f;
        bool safe = isfinite(fx0) && isfinite(fx1) && isfinite(fy0) && isfinite(fy1)
                    && fabsf(N) > 1e-6f;
        int4 bb;
        if (safe) {
            int x0 = (fx0 < 0.0f) ? 0 : ((fx0 > (float)(RES-1)) ? RES : (int)fx0);
            int x1 = (fx1 > (float)(RES-1)) ? (RES-1) : ((fx1 < 0.0f) ? -1 : (int)fx1);
            int y0 = (fy0 < 0.0f) ? 0 : ((fy0 > (float)(RES-1)) ? RES : (int)fy0);
            int y1 = (fy1 > (float)(RES-1)) ? (RES-1) : ((fy1 < 0.0f) ? -1 : (int)fy1);
            if (x0 > x1 || y0 > y1) { x0 = RES; x1 = -1; y0 = RES; y1 = -1; }
            bb = make_int4(x0, x1, y0, y1);
        } else {
            bb = make_int4(0, RES-1, 0, RES-1);
        }

        float kap = 0.0f;
        kap = fmaxf(kap, fabsf(c.A0)); kap = fmaxf(kap, 256.0f*fabsf(c.B0)); kap = fmaxf(kap, 256.0f*fabsf(c.C0));
        kap = fmaxf(kap, fabsf(c.A1)); kap = fmaxf(kap, 256.0f*fabsf(c.B1)); kap = fmaxf(kap, 256.0f*fabsf(c.C1));
        kap = fmaxf(kap, fabsf(c.A2)); kap = fmaxf(kap, 256.0f*fabsf(c.B2)); kap = fmaxf(kap, 256.0f*fabsf(c.C2));
        float rk = (kap > 1e-30f) ? (1.0f / kap) : 0.0f;
        Coef nn;
        nn.A0 = c.A0*rk; nn.B0 = c.B0*rk; nn.C0 = c.C0*rk;
        nn.A1 = c.A1*rk; nn.B1 = c.B1*rk; nn.C1 = c.C1*rk;
        nn.A2 = c.A2*rk; nn.B2 = c.B2*rk; nn.C2 = c.C2*rk;

        sC = c; sN = nn; sBB = bb; sFlag = inter ? 1 : 0;
    }
    __syncthreads();

    const Coef c  = sC;
    const Coef n  = sN;
    const int4 bb = sBB;

    // ---- phase 1: analytic per-row max (identical in all YSPLIT siblings) --
    float mx = 0.0f;
    for (int y = bb.z + tid; y <= bb.w; y += 256)
        mx = fmaxf(mx, row_max(c, n, bb, y));

    #pragma unroll
    for (int o = 16; o > 0; o >>= 1)
        mx = fmaxf(mx, __shfl_xor_sync(0xffffffffu, mx, o));
    if ((tid & 31) == 0) swmax[tid >> 5] = mx;
    __syncthreads();
    if (tid == 0) {
        float rmx = swmax[0];
        #pragma unroll
        for (int i = 1; i < 8; i++) rmx = fmaxf(rmx, swmax[i]);
        float mn = 0.0f;
        if (sFlag) {   // quasi-concave => grid min at an image corner
            const float e = (float)(RES - 1);
            mn = eval_s(c, 0.0f, 0.0f);
            mn = fminf(mn, eval_s(c, e, 0.0f));
            mn = fminf(mn, eval_s(c, 0.0f, e));
            mn = fminf(mn, eval_s(c, e, e));
        }
        sMn  = mn;
        sInv = 1.0f / (rmx - mn + EPSF);
    }
    __syncthreads();

    const float mn  = sMn;
    const float inv = sInv;

    // ---- phase 2: interval scatter, this block's share of row-pairs --------
    const int wid  = tid >> 5;
    const int lane = tid & 31;
    const int k0 = bb.z >> 1;
    const int k1 = bb.w >> 1;
    unsigned long long* __restrict__ acc = g_accum + (size_t)b * NPAIR;

    for (int k = k0 + (int)(blockIdx.y * 8 + wid); k <= k1; k += 8 * YSPLIT) {
        const int   y0 = 2 * k, y1 = 2 * k + 1;
        const float fy0 = (float)y0, fy1 = (float)y1;

        float lo0, hi0, lo1, hi1;
        row_iv(n, fy0, lo0, hi0);
        row_iv(n, fy1, lo1, hi1);
        if (y0 < bb.z) { lo0 = 1e30f; hi0 = -1e30f; }
        if (y1 > bb.w) { lo1 = 1e30f; hi1 = -1e30f; }

        float xsf = fmaxf((float)bb.x, ceilf(fminf(lo0, lo1)) - 1.0f);
        float xef = fminf((float)bb.y, floorf(fmaxf(hi0, hi1)) + 1.0f);
        const int xs = (int)xsf;
        const int xe = (int)xef;

        for (int x = xs + lane; x <= xe; x += 32) {
            const float fx = (float)x;
            unsigned int v0 = 0u, v1 = 0u;
            float d0 = eval_s(c, fx, fy0) - mn;
            if (d0 > 0.0f) v0 = __float2uint_rn(tanh_pade(d0 * inv) * SCALEF);
            float d1 = eval_s(c, fx, fy1) - mn;
            if (d1 > 0.0f) v1 = __float2uint_rn(tanh_pade(d1 * inv) * SCALEF);
            unsigned long long p = (unsigned long long)v0
                                 | ((unsigned long long)v1 << 32);
            if (p) atomicAdd(acc + x * (RES / 2) + k, p);
        }
    }
}

// ---------------------------------------------------------------------------
// finalize: unpack fixed point -> float output AND reset accumulator to zero
// (so the next graph replay starts from a clean state; no zero_kernel needed).
// Each thread handles 2 u64 pairs for fewer, fatter memory ops.
// ---------------------------------------------------------------------------
__global__ void finalize_kernel(float* __restrict__ out)
{
    const int i2 = blockIdx.x * blockDim.x + threadIdx.x;   // pair-of-pairs idx
    const int i  = i2 * 2;
    if (i >= NBATCH * NPAIR) return;

    ulonglong2 p = *(ulonglong2*)(g_accum + i);
    *(ulonglong2*)(g_accum + i) = make_ulonglong2(0ull, 0ull);

    const int b = i / NPAIR;
    const int r = i - b * NPAIR;          // r = x*128 + k, k even here (i even)
    const int x = r >> 7;
    const int k = r & 127;
    float* o = out + (size_t)b * NPIX + x * RES + 2 * k;
    o[0] = (float)(unsigned int)(p.x)       * INVSCALE;
    o[1] = (float)(unsigned int)(p.x >> 32) * INVSCALE;
    o[2] = (float)(unsigned int)(p.y)       * INVSCALE;
    o[3] = (float)(unsigned int)(p.y >> 32) * INVSCALE;
}

// ---------------------------------------------------------------------------
extern "C" void kernel_launch(void* const* d_in, const int* in_sizes, int n_in,
                              void* d_out, int out_size)
{
    const float* meshes = (const float*)d_in[0];
    const float* K      = (const float*)d_in[1];
    const int*   idxs   = (const int*)  d_in[2];
    const float* poses  = (const float*)d_in[3];
    float*       out    = (float*)d_out;

    dim3 g(NBATCH * NTRI, YSPLIT);
    fused_kernel<<<g, 256>>>(meshes, K, idxs, poses);
    finalize_kernel<<<(NBATCH * NPAIR / 2 + 255) / 256, 256>>>(out);
}